// round 2
// baseline (speedup 1.0000x reference)
#include <cuda_runtime.h>

// Problem constants
#define BATCH   2
#define NPEAK   128
#define NCHUNK  256            // BATCH * NPEAK
#define CHLEN   512
#define HID     256
#define MDIM    283
#define DEPTH   7
#define HL      ((size_t)HID * CHLEN)          // 131072 elems per chunk
#define BUF_ELEMS ((size_t)NCHUNK * HID * CHLEN)

// Ping-pong scratch (no allocations allowed; __device__ globals are the sanctioned path)
__device__ float g_bufA[BUF_ELEMS];
__device__ float g_bufB[BUF_ELEMS];

// ---------------------------------------------------------------------------
// Projection: h[n,c,l] = sum_m x[b, p*512+l, m] * w_proj[c, m]
// Tile: 64 C x 128 L per block, 256 threads, 4x8 outputs/thread.
// ---------------------------------------------------------------------------
__global__ __launch_bounds__(256) void proj_kernel(
    const float* __restrict__ x, const float* __restrict__ wp, float* __restrict__ out)
{
    __shared__ float Ws[8][64];
    __shared__ float Xs[8][128];
    const int ltile = blockIdx.x, ctile = blockIdx.y, n = blockIdx.z;
    const int tid = threadIdx.x;
    const int ty = tid >> 4, tx = tid & 15;
    const int b = n >> 7, p = n & 127;
    const float* xbase = x + ((size_t)b * 65536 + (size_t)p * 512 + (size_t)ltile * 128) * MDIM;

    float acc[4][8];
#pragma unroll
    for (int i = 0; i < 4; i++)
#pragma unroll
        for (int j = 0; j < 8; j++) acc[i][j] = 0.f;

    const int lld = tid >> 1;      // 0..127 : tile-local l this thread loads
    const int mh  = tid & 1;       // which half of the 8-wide k slab

    for (int k0 = 0; k0 < MDIM; k0 += 8) {
        {   // weight tile: 8 k x 64 c
            int idx = tid;
#pragma unroll
            for (int r = 0; r < 2; r++) {
                int kk = idx >> 6, c = idx & 63;
                int k = k0 + kk;
                Ws[kk][c] = (k < MDIM) ? wp[(size_t)(ctile * 64 + c) * MDIM + k] : 0.f;
                idx += 256;
            }
        }
        {   // x tile: 128 l x 8 m (each thread: 4 consecutive m of one l)
            const float* xr = xbase + (size_t)lld * MDIM + k0 + mh * 4;
#pragma unroll
            for (int j = 0; j < 4; j++) {
                int k = k0 + mh * 4 + j;
                Xs[mh * 4 + j][lld] = (k < MDIM) ? xr[j] : 0.f;
            }
        }
        __syncthreads();
#pragma unroll
        for (int kk = 0; kk < 8; kk++) {
            float4 a  = *(const float4*)&Ws[kk][ty * 4];
            float4 v0 = *(const float4*)&Xs[kk][tx * 4];
            float4 v1 = *(const float4*)&Xs[kk][tx * 4 + 64];
            float av[4] = {a.x, a.y, a.z, a.w};
            float xv[8] = {v0.x, v0.y, v0.z, v0.w, v1.x, v1.y, v1.z, v1.w};
#pragma unroll
            for (int i = 0; i < 4; i++)
#pragma unroll
                for (int j = 0; j < 8; j++) acc[i][j] = fmaf(av[i], xv[j], acc[i][j]);
        }
        __syncthreads();
    }
    float* ob = out + (size_t)n * HL + (size_t)(ctile * 64 + ty * 4) * CHLEN
                + ltile * 128 + tx * 4;
#pragma unroll
    for (int i = 0; i < 4; i++) {
        *(float4*)&ob[i * CHLEN]      = make_float4(acc[i][0], acc[i][1], acc[i][2], acc[i][3]);
        *(float4*)&ob[i * CHLEN + 64] = make_float4(acc[i][4], acc[i][5], acc[i][6], acc[i][7]);
    }
}

// ---------------------------------------------------------------------------
// Dilated conv layer + GELU residual:
//   c[n,o,l] = b[o] + sum_{i,t} w[o,i,t] * h[n,i,l+(t-1)*d]   (zero pad per chunk)
//   out = gelu(c) + c
// Tile: 64 O x 128 L per block; K-loop over 32 slabs of (8 in-ch x 3 taps).
// ---------------------------------------------------------------------------
__global__ __launch_bounds__(256) void conv_kernel(
    const float* __restrict__ in, const float* __restrict__ w,
    const float* __restrict__ bias, float* __restrict__ out, int d)
{
    __shared__ float Ws[24][64];
    __shared__ float Hs[24][128];
    const int ltile = blockIdx.x, otile = blockIdx.y, n = blockIdx.z;
    const int tid = threadIdx.x;
    const int ty = tid >> 4, tx = tid & 15;
    const float* hin = in + (size_t)n * HL;

    float acc[4][8];
#pragma unroll
    for (int i = 0; i < 4; i++)
#pragma unroll
        for (int j = 0; j < 8; j++) acc[i][j] = 0.f;

    for (int kc = 0; kc < 32; kc++) {
        {   // weight tile: 24 (k,t) rows x 64 o
            int idx = tid;
#pragma unroll
            for (int r = 0; r < 6; r++) {
                int row = idx >> 6;           // 0..23
                int o   = idx & 63;
                int kk  = row / 3, t = row - kk * 3;
                Ws[row][o] = w[((size_t)(otile * 64 + o) * HID + kc * 8 + kk) * 3 + t];
                idx += 256;
            }
        }
        {   // activation tile: 24 rows x 128 l (with shift + zero pad)
            int idx = tid;
#pragma unroll
            for (int r = 0; r < 12; r++) {
                int row = idx >> 7;           // 0..23
                int l   = idx & 127;
                int kk  = row / 3, t = row - kk * 3;
                int lp  = ltile * 128 + l + (t - 1) * d;
                Hs[row][l] = (lp >= 0 && lp < CHLEN)
                             ? hin[(size_t)(kc * 8 + kk) * CHLEN + lp] : 0.f;
                idx += 256;
            }
        }
        __syncthreads();
#pragma unroll
        for (int ks = 0; ks < 24; ks++) {
            float4 a  = *(const float4*)&Ws[ks][ty * 4];
            float4 v0 = *(const float4*)&Hs[ks][tx * 4];
            float4 v1 = *(const float4*)&Hs[ks][tx * 4 + 64];
            float av[4] = {a.x, a.y, a.z, a.w};
            float xv[8] = {v0.x, v0.y, v0.z, v0.w, v1.x, v1.y, v1.z, v1.w};
#pragma unroll
            for (int i = 0; i < 4; i++)
#pragma unroll
                for (int j = 0; j < 8; j++) acc[i][j] = fmaf(av[i], xv[j], acc[i][j]);
        }
        __syncthreads();
    }

    float* ob = out + (size_t)n * HL + (size_t)(otile * 64 + ty * 4) * CHLEN
                + ltile * 128 + tx * 4;
#pragma unroll
    for (int i = 0; i < 4; i++) {
        float bz = bias[otile * 64 + ty * 4 + i];
        float r[8];
#pragma unroll
        for (int j = 0; j < 8; j++) {
            float c = acc[i][j] + bz;
            r[j] = c * normcdff(c) + c;   // exact gelu(c) + c
        }
        *(float4*)&ob[i * CHLEN]      = make_float4(r[0], r[1], r[2], r[3]);
        *(float4*)&ob[i * CHLEN + 64] = make_float4(r[4], r[5], r[6], r[7]);
    }
}

// ---------------------------------------------------------------------------
// Profile head: K=20 conv, 256 -> 1 channels, pad (9,10).
// One block per chunk; each thread owns 2 output positions.
// ---------------------------------------------------------------------------
__global__ __launch_bounds__(256) void profile_kernel(
    const float* __restrict__ h, const float* __restrict__ wprof,
    const float* __restrict__ bprof, float* __restrict__ out)
{
    __shared__ float hrow[544];    // l' = -9 .. 521  -> index l'+9 in [0, 531)
    __shared__ float wsh[HID * 20];
    const int n = blockIdx.x, tid = threadIdx.x;
    for (int i = tid; i < HID * 20; i += 256) wsh[i] = wprof[i];

    const float* hb = h + (size_t)n * HL;
    float acc0 = 0.f, acc1 = 0.f;
    for (int c = 0; c < HID; c++) {
        __syncthreads();
        for (int i = tid; i < 531; i += 256) {
            int lp = i - 9;
            hrow[i] = (lp >= 0 && lp < CHLEN) ? hb[(size_t)c * CHLEN + lp] : 0.f;
        }
        __syncthreads();
        const float* wc = &wsh[c * 20];
#pragma unroll
        for (int k = 0; k < 20; k++) {
            acc0 = fmaf(wc[k], hrow[tid + k], acc0);         // h[l + k - 9]
            acc1 = fmaf(wc[k], hrow[tid + 256 + k], acc1);
        }
    }
    float bz = bprof[0];
    out[256 + (size_t)n * CHLEN + tid]       = acc0 + bz;
    out[256 + (size_t)n * CHLEN + tid + 256] = acc1 + bz;
}

// ---------------------------------------------------------------------------
// atpm head: mean over length, dot with w_atpm, mask by n_peaks (int32 —
// JAX default x64-disabled downgrades the reference's int64 to int32).
// ---------------------------------------------------------------------------
__global__ __launch_bounds__(256) void atpm_kernel(
    const float* __restrict__ h, const float* __restrict__ watpm,
    const float* __restrict__ batpm, const int* __restrict__ npeaks,
    float* __restrict__ out)
{
    __shared__ float red[256];
    const int n = blockIdx.x, tid = threadIdx.x;
    const float* hb = h + (size_t)n * HL + (size_t)tid * CHLEN;
    float s = 0.f;
    for (int l = 0; l < CHLEN; l++) s += hb[l];
    s *= watpm[tid];
    red[tid] = s;
    __syncthreads();
    for (int off = 128; off > 0; off >>= 1) {
        if (tid < off) red[tid] += red[tid + off];
        __syncthreads();
    }
    if (tid == 0) {
        float v = red[0] * (1.f / (float)CHLEN) + batpm[0];
        int b = n >> 7, p = n & 127;
        out[n] = (p < npeaks[b]) ? v : 0.f;
    }
}

// ---------------------------------------------------------------------------
extern "C" void kernel_launch(void* const* d_in, const int* in_sizes, int n_in,
                              void* d_out, int out_size)
{
    const float* x       = (const float*)d_in[0];
    const float* w_proj  = (const float*)d_in[1];
    const float* tower_w = (const float*)d_in[2];
    const float* tower_b = (const float*)d_in[3];
    const float* w_prof  = (const float*)d_in[4];
    const float* b_prof  = (const float*)d_in[5];
    const float* w_atpm  = (const float*)d_in[6];
    const float* b_atpm  = (const float*)d_in[7];
    const int*   n_peaks = (const int*)d_in[8];
    float* out = (float*)d_out;

    float *pA, *pB;
    cudaGetSymbolAddress((void**)&pA, g_bufA);
    cudaGetSymbolAddress((void**)&pB, g_bufB);

    dim3 grid(4, 4, NCHUNK);     // (l-tiles, c/o-tiles, chunks)
    proj_kernel<<<grid, 256>>>(x, w_proj, pA);

    float* cur = pA;
    float* nxt = pB;
    for (int i = 0; i < DEPTH; i++) {
        int d = 2 << i;          // 2^(i+1)
        conv_kernel<<<grid, 256>>>(cur, tower_w + (size_t)i * HID * HID * 3,
                                   tower_b + i * HID, nxt, d);
        float* t = cur; cur = nxt; nxt = t;
    }

    profile_kernel<<<NCHUNK, 256>>>(cur, w_prof, b_prof, out);
    atpm_kernel<<<NCHUNK, 256>>>(cur, w_atpm, b_atpm, n_peaks, out);
}

// round 5
// speedup vs baseline: 2.0259x; 2.0259x over previous
#include <cuda_runtime.h>
#include <cuda_bf16.h>
#include <cstdint>

// Problem constants
#define NCHUNK  256            // BATCH * NPEAK
#define CHLEN   512
#define HID     256
#define MDIM    283
#define DEPTH   7
#define HLC     131072         // CHLEN * HID elements per chunk, [l][c] layout
#define BUF_ELEMS ((size_t)NCHUNK * HLC)

// Activation ping-pong buffers, split bf16 (hi + lo reconstructs fp32 to ~2^-18)
__device__ __nv_bfloat16 g_hiA[BUF_ELEMS];
__device__ __nv_bfloat16 g_loA[BUF_ELEMS];
__device__ __nv_bfloat16 g_hiB[BUF_ELEMS];
__device__ __nv_bfloat16 g_loB[BUF_ELEMS];

// Pre-split tower weights: [layer][tap][o][i], bf16 hi/lo
#define WPLANE 65536                               // 256*256 per (layer,tap)
__device__ __nv_bfloat16 g_wHi[DEPTH * 3 * WPLANE];
__device__ __nv_bfloat16 g_wLo[DEPTH * 3 * WPLANE];

__device__ __forceinline__ uint32_t smem_u32(const void* p) {
    uint32_t a;
    asm("{ .reg .u64 t; cvta.to.shared.u64 t, %1; cvt.u32.u64 %0, t; }" : "=r"(a) : "l"(p));
    return a;
}
__device__ __forceinline__ void split_bf16(float v, __nv_bfloat16& h, __nv_bfloat16& l) {
    h = __float2bfloat16(v);
    l = __float2bfloat16(v - __bfloat162float(h));
}
struct alignas(8) bf4 { __nv_bfloat16 a, b, c, d; };

__device__ __forceinline__ void ldsm_x4(uint32_t* r, uint32_t addr) {
    asm volatile("ldmatrix.sync.aligned.m8n8.x4.shared.b16 {%0,%1,%2,%3}, [%4];"
        : "=r"(r[0]), "=r"(r[1]), "=r"(r[2]), "=r"(r[3]) : "r"(addr));
}
__device__ __forceinline__ void mma_16816(float* d, const uint32_t* a, const uint32_t* b) {
    asm volatile("mma.sync.aligned.m16n8k16.row.col.f32.bf16.bf16.f32 "
        "{%0,%1,%2,%3},{%4,%5,%6,%7},{%8,%9},{%0,%1,%2,%3};"
        : "+f"(d[0]), "+f"(d[1]), "+f"(d[2]), "+f"(d[3])
        : "r"(a[0]), "r"(a[1]), "r"(a[2]), "r"(a[3]), "r"(b[0]), "r"(b[1]));
}

// ---------------------------------------------------------------------------
// Weight prep: split fp32 tower weights into bf16 hi/lo, K-major [layer][t][o][i]
// ---------------------------------------------------------------------------
__global__ __launch_bounds__(256) void wprep_kernel(
    const float* __restrict__ w, __nv_bfloat16* __restrict__ whi,
    __nv_bfloat16* __restrict__ wlo)
{
    size_t j = (size_t)blockIdx.x * 256 + threadIdx.x;     // < DEPTH*3*WPLANE
    int layer = (int)(j / (3 * WPLANE));
    int rem   = (int)(j % (3 * WPLANE));
    int t  = rem / WPLANE;
    int oi = rem % WPLANE;                                  // o*256 + i
    float v = w[(size_t)layer * 3 * WPLANE + (size_t)oi * 3 + t];
    __nv_bfloat16 h, l;
    split_bf16(v, h, l);
    whi[j] = h;
    wlo[j] = l;
}

// ---------------------------------------------------------------------------
// Projection (SIMT fp32): h[n,l,c] = sum_m x[b, p*512+l, m] * w_proj[c, m]
// Writes split bf16 in [n][l][c] layout.
// ---------------------------------------------------------------------------
__global__ __launch_bounds__(256) void proj_kernel(
    const float* __restrict__ x, const float* __restrict__ wp,
    __nv_bfloat16* __restrict__ out_hi, __nv_bfloat16* __restrict__ out_lo)
{
    __shared__ float Ws[8][64];
    __shared__ float Xs[8][128];
    const int ltile = blockIdx.x, ctile = blockIdx.y, n = blockIdx.z;
    const int tid = threadIdx.x;
    const int ty = tid >> 4, tx = tid & 15;
    const int b = n >> 7, p = n & 127;
    const float* xbase = x + ((size_t)b * 65536 + (size_t)p * 512 + (size_t)ltile * 128) * MDIM;

    float acc[4][8];
#pragma unroll
    for (int i = 0; i < 4; i++)
#pragma unroll
        for (int j = 0; j < 8; j++) acc[i][j] = 0.f;

    const int lld = tid >> 1;
    const int mh  = tid & 1;

    for (int k0 = 0; k0 < MDIM; k0 += 8) {
        {
            int idx = tid;
#pragma unroll
            for (int r = 0; r < 2; r++) {
                int kk = idx >> 6, c = idx & 63;
                int k = k0 + kk;
                Ws[kk][c] = (k < MDIM) ? wp[(size_t)(ctile * 64 + c) * MDIM + k] : 0.f;
                idx += 256;
            }
        }
        {
            const float* xr = xbase + (size_t)lld * MDIM + k0 + mh * 4;
#pragma unroll
            for (int j = 0; j < 4; j++) {
                int k = k0 + mh * 4 + j;
                Xs[mh * 4 + j][lld] = (k < MDIM) ? xr[j] : 0.f;
            }
        }
        __syncthreads();
#pragma unroll
        for (int kk = 0; kk < 8; kk++) {
            float4 a  = *(const float4*)&Ws[kk][ty * 4];
            float4 v0 = *(const float4*)&Xs[kk][tx * 4];
            float4 v1 = *(const float4*)&Xs[kk][tx * 4 + 64];
            float av[4] = {a.x, a.y, a.z, a.w};
            float xv[8] = {v0.x, v0.y, v0.z, v0.w, v1.x, v1.y, v1.z, v1.w};
#pragma unroll
            for (int i = 0; i < 4; i++)
#pragma unroll
                for (int j = 0; j < 8; j++) acc[i][j] = fmaf(av[i], xv[j], acc[i][j]);
        }
        __syncthreads();
    }

    const int c0 = ctile * 64 + ty * 4;
#pragma unroll
    for (int j = 0; j < 8; j++) {
        int lcol = ltile * 128 + tx * 4 + ((j < 4) ? j : 60 + j);
        bf4 vh, vl;
        split_bf16(acc[0][j], vh.a, vl.a);
        split_bf16(acc[1][j], vh.b, vl.b);
        split_bf16(acc[2][j], vh.c, vl.c);
        split_bf16(acc[3][j], vh.d, vl.d);
        size_t off = (size_t)n * HLC + (size_t)lcol * HID + c0;
        *(bf4*)(out_hi + off) = vh;
        *(bf4*)(out_lo + off) = vl;
    }
}

// ---------------------------------------------------------------------------
// Dilated conv layer via mma.sync bf16 split-precision (3 passes).
// CTA: 128 o x 128 l; 8 warps (2x4), warp tile 64 o x 32 l.
// ---------------------------------------------------------------------------
#define LDA     72
#define ABUF    18432
#define SM_B    110592
#define SM_CONV 147456

__global__ __launch_bounds__(256) void conv_mma_kernel(
    const __nv_bfloat16* __restrict__ in_hi, const __nv_bfloat16* __restrict__ in_lo,
    const __nv_bfloat16* __restrict__ whi, const __nv_bfloat16* __restrict__ wlo,
    const float* __restrict__ bias,
    __nv_bfloat16* __restrict__ out_hi, __nv_bfloat16* __restrict__ out_lo, int d)
{
    extern __shared__ char smem[];
    const uint32_t sb = smem_u32(smem);
    const int tid = threadIdx.x;
    const int wid = tid >> 5, lane = tid & 31;
    const int warp_m = wid >> 2, warp_n = wid & 3;
    const int ltile = blockIdx.x, otile = blockIdx.y, n = blockIdx.z;

    const __nv_bfloat16* Hh = in_hi + (size_t)n * HLC;
    const __nv_bfloat16* Hl = in_lo + (size_t)n * HLC;

    float acc[4][4][4];
#pragma unroll
    for (int mi = 0; mi < 4; mi++)
#pragma unroll
        for (int ni = 0; ni < 4; ni++)
#pragma unroll
            for (int e = 0; e < 4; e++) acc[mi][ni][e] = 0.f;

    // ldmatrix lane addressing (element offsets into a [row][LDA] bf16 tile)
    const int aRow   = warp_m * 64 + (lane & 15);
    const int aCol   = (lane >> 4) << 3;
    const int bRow   = warp_n * 32 + ((lane & 7) | ((lane >> 4) << 3));
    const int bCol   = ((lane >> 3) & 1) << 3;

#pragma unroll 1
    for (int i0 = 0; i0 < HID; i0 += 64) {
        // ---- fill A: 3 taps x hi/lo, 128 o-rows x 64 i-cols (uint4 copies)
        __syncthreads();                       // prior mma done with A and B
        for (int idx = tid; idx < 3072; idx += 256) {
            const int t  = idx >> 10;
            const int r  = (idx >> 3) & 127;
            const int ch = idx & 7;
            const size_t gsrc = (size_t)t * WPLANE + (size_t)(otile * 128 + r) * HID + i0 + ch * 8;
            const uint32_t sdst = (uint32_t)(t * 2) * ABUF + (uint32_t)(r * LDA + ch * 8) * 2;
            *(uint4*)(smem + sdst)        = *(const uint4*)(whi + gsrc);
            *(uint4*)(smem + sdst + ABUF) = *(const uint4*)(wlo + gsrc);
        }

#pragma unroll 1
        for (int t = 0; t < 3; t++) {
            const int shift = (t - 1) * d;
            if (t > 0) __syncthreads();        // prior tap's mma done with B
            // ---- fill B: 128 l-rows x 64 i-cols, shifted + zero-padded
            for (int idx = tid; idx < 1024; idx += 256) {
                const int r  = idx >> 3;
                const int ch = idx & 7;
                const int lsrc = ltile * 128 + r + shift;
                uint4 vh = make_uint4(0, 0, 0, 0), vl = vh;
                if (lsrc >= 0 && lsrc < CHLEN) {
                    const size_t goff = (size_t)lsrc * HID + i0 + ch * 8;
                    vh = *(const uint4*)(Hh + goff);
                    vl = *(const uint4*)(Hl + goff);
                }
                const uint32_t sdst = SM_B + (uint32_t)(r * LDA + ch * 8) * 2;
                *(uint4*)(smem + sdst)        = vh;
                *(uint4*)(smem + sdst + ABUF) = vl;
            }
            __syncthreads();

            const uint32_t aHiBase = sb + (uint32_t)(t * 2) * ABUF;
            const uint32_t bHiBase = sb + SM_B;
#pragma unroll
            for (int ks = 0; ks < 4; ks++) {
                uint32_t ah[4][4], al[4][4], bh[8], bl[8];
#pragma unroll
                for (int mi = 0; mi < 4; mi++) {
                    const uint32_t off =
                        (uint32_t)(((aRow + mi * 16) * LDA) + aCol + ks * 16) * 2;
                    ldsm_x4(ah[mi], aHiBase + off);
                    ldsm_x4(al[mi], aHiBase + ABUF + off);
                }
#pragma unroll
                for (int bi = 0; bi < 2; bi++) {
                    const uint32_t off =
                        (uint32_t)(((bRow + bi * 16) * LDA) + bCol + ks * 16) * 2;
                    ldsm_x4(&bh[bi * 4], bHiBase + off);
                    ldsm_x4(&bl[bi * 4], bHiBase + ABUF + off);
                }
#pragma unroll
                for (int mi = 0; mi < 4; mi++)
#pragma unroll
                    for (int ni = 0; ni < 4; ni++) {
                        mma_16816(acc[mi][ni], ah[mi], &bh[ni * 2]);  // hi*hi
                        mma_16816(acc[mi][ni], ah[mi], &bl[ni * 2]);  // hi*lo
                        mma_16816(acc[mi][ni], al[mi], &bh[ni * 2]);  // lo*hi
                    }
            }
        }
    }

    // ---- epilogue: bias + exact gelu + residual, stage [l][o] in smem, store
    __syncthreads();
    __nv_bfloat16* stage_hi = (__nv_bfloat16*)smem;            // [128 l][136 o]
    __nv_bfloat16* stage_lo = (__nv_bfloat16*)(smem + 36864);
    const int g = lane >> 2, tg = lane & 3;
#pragma unroll
    for (int mi = 0; mi < 4; mi++) {
        const int row0 = warp_m * 64 + mi * 16 + g;
        const float b0 = bias[otile * 128 + row0];
        const float b8 = bias[otile * 128 + row0 + 8];
#pragma unroll
        for (int ni = 0; ni < 4; ni++) {
            const int col = warp_n * 32 + ni * 8 + tg * 2;
#pragma unroll
            for (int e = 0; e < 4; e++) {
                const int row = row0 + ((e >> 1) << 3);
                const int c   = col + (e & 1);
                float v = acc[mi][ni][e] + ((e < 2) ? b0 : b8);
                float r = fmaf(v, normcdff(v), v);             // gelu(v) + v
                __nv_bfloat16 h, l;
                split_bf16(r, h, l);
                stage_hi[c * 136 + row] = h;
                stage_lo[c * 136 + row] = l;
            }
        }
    }
    __syncthreads();
    {
        const int row  = tid >> 1;                              // l-local
        const int half = tid & 1;                               // o 64-half
        const char* sh = (const char*)stage_hi + row * 272 + half * 128;
        const char* sl = (const char*)stage_lo + row * 272 + half * 128;
        __nv_bfloat16* oh = out_hi + (size_t)n * HLC +
                            (size_t)(ltile * 128 + row) * HID + otile * 128 + half * 64;
        __nv_bfloat16* ol = out_lo + (size_t)n * HLC +
                            (size_t)(ltile * 128 + row) * HID + otile * 128 + half * 64;
#pragma unroll
        for (int k = 0; k < 8; k++) {                           // 64 bf16 = 8 uint4 (was 4: bug)
            ((uint4*)oh)[k] = ((const uint4*)sh)[k];
            ((uint4*)ol)[k] = ((const uint4*)sl)[k];
        }
    }
}

// ---------------------------------------------------------------------------
// Profile head, [l][c] layout: out[l] = b + sum_k sum_c w[c][k] h[l+k-9][c]
// ---------------------------------------------------------------------------
#define PROF_Q_ROWS 531
#define PROF_SMEM   (PROF_Q_ROWS * 20 * 4 + 16 + HID * 20 * 4)

__global__ __launch_bounds__(256) void profile_head_kernel(
    const __nv_bfloat16* __restrict__ in_hi, const __nv_bfloat16* __restrict__ in_lo,
    const float* __restrict__ wprof, const float* __restrict__ bprof,
    float* __restrict__ out)
{
    extern __shared__ char smem[];
    float* Qs  = (float*)smem;                         // [531][20]
    float* wsh = (float*)(smem + PROF_Q_ROWS * 20 * 4 + 16);
    const int n = blockIdx.x, tid = threadIdx.x;
    const int wid = tid >> 5, lane = tid & 31;

    for (int i = tid; i < HID * 20; i += 256) wsh[i] = wprof[i];
    for (int i = tid; i < PROF_Q_ROWS * 20; i += 256) Qs[i] = 0.f;
    __syncthreads();

    const __nv_bfloat16* Hh = in_hi + (size_t)n * HLC;
    const __nv_bfloat16* Hl = in_lo + (size_t)n * HLC;
    for (int row = wid; row < CHLEN; row += 8) {
        uint4 uh = *(const uint4*)(Hh + (size_t)row * HID + lane * 8);
        uint4 ul = *(const uint4*)(Hl + (size_t)row * HID + lane * 8);
        const __nv_bfloat16* ph = (const __nv_bfloat16*)&uh;
        const __nv_bfloat16* pl = (const __nv_bfloat16*)&ul;
        float acc[20];
#pragma unroll
        for (int k = 0; k < 20; k++) acc[k] = 0.f;
#pragma unroll
        for (int cc = 0; cc < 8; cc++) {
            float hv = __bfloat162float(ph[cc]) + __bfloat162float(pl[cc]);
            const float* wr = &wsh[(lane * 8 + cc) * 20];
#pragma unroll
            for (int k = 0; k < 20; k++) acc[k] = fmaf(hv, wr[k], acc[k]);
        }
#pragma unroll
        for (int off = 16; off > 0; off >>= 1)
#pragma unroll
            for (int k = 0; k < 20; k++)
                acc[k] += __shfl_xor_sync(0xFFFFFFFF, acc[k], off);
        if (lane < 20) Qs[(row + 9) * 20 + lane] = acc[lane];
    }
    __syncthreads();

    const float bz = bprof[0];
    for (int l = tid; l < CHLEN; l += 256) {
        float s = bz;
#pragma unroll
        for (int k = 0; k < 20; k++) s += Qs[(l + k) * 20 + k];
        out[NCHUNK + (size_t)n * CHLEN + l] = s;
    }
}

// ---------------------------------------------------------------------------
// atpm head, [l][c] layout; n_peaks is int32 (JAX x64-disabled)
// ---------------------------------------------------------------------------
__global__ __launch_bounds__(256) void atpm_head_kernel(
    const __nv_bfloat16* __restrict__ in_hi, const __nv_bfloat16* __restrict__ in_lo,
    const float* __restrict__ watpm, const float* __restrict__ batpm,
    const int* __restrict__ npeaks, float* __restrict__ out)
{
    __shared__ float red[256];
    const int n = blockIdx.x, tid = threadIdx.x;
    const __nv_bfloat16* Hh = in_hi + (size_t)n * HLC + tid;
    const __nv_bfloat16* Hl = in_lo + (size_t)n * HLC + tid;
    float s = 0.f;
    for (int l = 0; l < CHLEN; l++)
        s += __bfloat162float(Hh[(size_t)l * HID]) + __bfloat162float(Hl[(size_t)l * HID]);
    red[tid] = s * watpm[tid];
    __syncthreads();
    for (int off = 128; off > 0; off >>= 1) {
        if (tid < off) red[tid] += red[tid + off];
        __syncthreads();
    }
    if (tid == 0) {
        float v = red[0] * (1.f / (float)CHLEN) + batpm[0];
        int b = n >> 7, p = n & 127;
        out[n] = (p < npeaks[b]) ? v : 0.f;
    }
}

// ---------------------------------------------------------------------------
extern "C" void kernel_launch(void* const* d_in, const int* in_sizes, int n_in,
                              void* d_out, int out_size)
{
    const float* x       = (const float*)d_in[0];
    const float* w_proj  = (const float*)d_in[1];
    const float* tower_w = (const float*)d_in[2];
    const float* tower_b = (const float*)d_in[3];
    const float* w_prof  = (const float*)d_in[4];
    const float* b_prof  = (const float*)d_in[5];
    const float* w_atpm  = (const float*)d_in[6];
    const float* b_atpm  = (const float*)d_in[7];
    const int*   n_peaks = (const int*)d_in[8];
    float* out = (float*)d_out;

    __nv_bfloat16 *hiA, *loA, *hiB, *loB, *wHi, *wLo;
    cudaGetSymbolAddress((void**)&hiA, g_hiA);
    cudaGetSymbolAddress((void**)&loA, g_loA);
    cudaGetSymbolAddress((void**)&hiB, g_hiB);
    cudaGetSymbolAddress((void**)&loB, g_loB);
    cudaGetSymbolAddress((void**)&wHi, g_wHi);
    cudaGetSymbolAddress((void**)&wLo, g_wLo);

    cudaFuncSetAttribute(conv_mma_kernel,
                         cudaFuncAttributeMaxDynamicSharedMemorySize, SM_CONV);
    cudaFuncSetAttribute(profile_head_kernel,
                         cudaFuncAttributeMaxDynamicSharedMemorySize, PROF_SMEM);

    wprep_kernel<<<DEPTH * 3 * WPLANE / 256, 256>>>(tower_w, wHi, wLo);
    proj_kernel<<<dim3(4, 4, NCHUNK), 256>>>(x, w_proj, hiA, loA);

    __nv_bfloat16 *ch = hiA, *cl = loA, *nh = hiB, *nl = loB;
    for (int i = 0; i < DEPTH; i++) {
        int d = 2 << i;          // 2^(i+1)
        conv_mma_kernel<<<dim3(4, 2, NCHUNK), 256, SM_CONV>>>(
            ch, cl, wHi + (size_t)i * 3 * WPLANE, wLo + (size_t)i * 3 * WPLANE,
            tower_b + i * HID, nh, nl, d);
        __nv_bfloat16* t;
        t = ch; ch = nh; nh = t;
        t = cl; cl = nl; nl = t;
    }

    profile_head_kernel<<<NCHUNK, 256, PROF_SMEM>>>(ch, cl, w_prof, b_prof, out);
    atpm_head_kernel<<<NCHUNK, 256>>>(ch, cl, w_atpm, b_atpm, n_peaks, out);
}

// round 7
// speedup vs baseline: 2.8738x; 1.4185x over previous
#include <cuda_runtime.h>
#include <cuda_bf16.h>
#include <cstdint>

// Problem constants
#define NCHUNK  256            // BATCH * NPEAK
#define CHLEN   512
#define HID     256
#define MDIM    283
#define KPADP   320            // proj K padded to 5*64
#define DEPTH   7
#define HLC     131072         // CHLEN * HID elements per chunk, [l][c] layout
#define NROWS   131072         // total l rows (NCHUNK * CHLEN)
#define BUF_ELEMS ((size_t)NCHUNK * HLC)

// Activation ping-pong buffers, split bf16 (hi + lo reconstructs fp32 to ~2^-18)
__device__ __nv_bfloat16 g_hiA[BUF_ELEMS];
__device__ __nv_bfloat16 g_loA[BUF_ELEMS];
__device__ __nv_bfloat16 g_hiB[BUF_ELEMS];
__device__ __nv_bfloat16 g_loB[BUF_ELEMS];

// Pre-split tower weights: [layer][tap][o][i], bf16 hi/lo
#define WPLANE 65536                               // 256*256 per (layer,tap)
__device__ __nv_bfloat16 g_wHi[DEPTH * 3 * WPLANE];
__device__ __nv_bfloat16 g_wLo[DEPTH * 3 * WPLANE];

// Pre-split x and w_proj, K padded to 320
__device__ __nv_bfloat16 g_xHi[(size_t)NROWS * KPADP];
__device__ __nv_bfloat16 g_xLo[(size_t)NROWS * KPADP];
__device__ __nv_bfloat16 g_wpHi[HID * KPADP];
__device__ __nv_bfloat16 g_wpLo[HID * KPADP];

__device__ __forceinline__ uint32_t smem_u32(const void* p) {
    uint32_t a;
    asm("{ .reg .u64 t; cvta.to.shared.u64 t, %1; cvt.u32.u64 %0, t; }" : "=r"(a) : "l"(p));
    return a;
}
__device__ __forceinline__ void split_bf16(float v, __nv_bfloat16& h, __nv_bfloat16& l) {
    h = __float2bfloat16(v);
    l = __float2bfloat16(v - __bfloat162float(h));
}
__device__ __forceinline__ void ldsm_x4(uint32_t* r, uint32_t addr) {
    asm volatile("ldmatrix.sync.aligned.m8n8.x4.shared.b16 {%0,%1,%2,%3}, [%4];"
        : "=r"(r[0]), "=r"(r[1]), "=r"(r[2]), "=r"(r[3]) : "r"(addr));
}
__device__ __forceinline__ void mma_16816(float* d, const uint32_t* a, const uint32_t* b) {
    asm volatile("mma.sync.aligned.m16n8k16.row.col.f32.bf16.bf16.f32 "
        "{%0,%1,%2,%3},{%4,%5,%6,%7},{%8,%9},{%0,%1,%2,%3};"
        : "+f"(d[0]), "+f"(d[1]), "+f"(d[2]), "+f"(d[3])
        : "r"(a[0]), "r"(a[1]), "r"(a[2]), "r"(a[3]), "r"(b[0]), "r"(b[1]));
}
__device__ __forceinline__ void cp16(uint32_t dst, const void* src, int srcsize) {
    asm volatile("cp.async.cg.shared.global [%0], [%1], 16, %2;"
                 :: "r"(dst), "l"(src), "r"(srcsize) : "memory");
}
__device__ __forceinline__ void cp_commit_wait() {
    asm volatile("cp.async.commit_group;" ::: "memory");
    asm volatile("cp.async.wait_group 0;" ::: "memory");
}

// ---------------------------------------------------------------------------
// Prep kernels
// ---------------------------------------------------------------------------
__global__ __launch_bounds__(256) void wprep_kernel(
    const float* __restrict__ w, __nv_bfloat16* __restrict__ whi,
    __nv_bfloat16* __restrict__ wlo)
{
    size_t j = (size_t)blockIdx.x * 256 + threadIdx.x;     // < DEPTH*3*WPLANE
    int layer = (int)(j / (3 * WPLANE));
    int rem   = (int)(j % (3 * WPLANE));
    int t  = rem / WPLANE;
    int oi = rem % WPLANE;                                  // o*256 + i
    float v = w[(size_t)layer * 3 * WPLANE + (size_t)oi * 3 + t];
    __nv_bfloat16 h, l;
    split_bf16(v, h, l);
    whi[j] = h;
    wlo[j] = l;
}

__global__ __launch_bounds__(256) void xsplit_kernel(
    const float* __restrict__ x, __nv_bfloat16* __restrict__ xh,
    __nv_bfloat16* __restrict__ xl)
{
    const size_t row = blockIdx.x;                          // < NROWS
    for (int m = threadIdx.x; m < KPADP; m += 256) {
        float v = (m < MDIM) ? x[row * MDIM + m] : 0.f;
        __nv_bfloat16 h, l;
        split_bf16(v, h, l);
        xh[row * KPADP + m] = h;
        xl[row * KPADP + m] = l;
    }
}

__global__ __launch_bounds__(256) void wpsplit_kernel(
    const float* __restrict__ wp, __nv_bfloat16* __restrict__ wh,
    __nv_bfloat16* __restrict__ wl)
{
    const size_t c = blockIdx.x;                            // < HID
    for (int m = threadIdx.x; m < KPADP; m += 256) {
        float v = (m < MDIM) ? wp[c * MDIM + m] : 0.f;
        __nv_bfloat16 h, l;
        split_bf16(v, h, l);
        wh[c * KPADP + m] = h;
        wl[c * KPADP + m] = l;
    }
}

// ---------------------------------------------------------------------------
// Shared mma tile geometry
// CTA: 128 rows(M) x 128 cols(N); 8 warps (2x4), warp tile 64x32.
// SMEM per phase: A hi/lo + B hi/lo, each 128 x 64 bf16 with LDA=72 pad.
// Total 73728 B -> 2 CTAs/SM.
// ---------------------------------------------------------------------------
#define LDA     72
#define ABUF    18432
#define SM_MMA  73728

// ---------------------------------------------------------------------------
// Projection via mma: D[c, row] = sum_m wp[c,m] x[row,m]; K=320, 5 phases.
// ---------------------------------------------------------------------------
__global__ __launch_bounds__(256, 2) void proj_mma_kernel(
    const __nv_bfloat16* __restrict__ xh, const __nv_bfloat16* __restrict__ xl,
    const __nv_bfloat16* __restrict__ wh, const __nv_bfloat16* __restrict__ wl,
    __nv_bfloat16* __restrict__ out_hi, __nv_bfloat16* __restrict__ out_lo)
{
    extern __shared__ char smem[];
    const uint32_t sb = smem_u32(smem);
    const uint32_t sbAh = sb, sbAl = sb + ABUF, sbBh = sb + 2 * ABUF, sbBl = sb + 3 * ABUF;
    const int tid = threadIdx.x;
    const int wid = tid >> 5, lane = tid & 31;
    const int warp_m = wid >> 2, warp_n = wid & 3;
    const int rtile = blockIdx.x;        // row tile (128 rows)
    const int otile = blockIdx.y;        // c half

    float acc[4][4][4];
#pragma unroll
    for (int mi = 0; mi < 4; mi++)
#pragma unroll
        for (int ni = 0; ni < 4; ni++)
#pragma unroll
            for (int e = 0; e < 4; e++) acc[mi][ni][e] = 0.f;

    const int aRow = warp_m * 64 + (lane & 15);
    const int aCol = (lane >> 4) << 3;
    const int bRow = warp_n * 32 + ((lane & 7) | ((lane >> 4) << 3));
    const int bCol = ((lane >> 3) & 1) << 3;

#pragma unroll 1
    for (int k0 = 0; k0 < KPADP; k0 += 64) {
        __syncthreads();
        for (int idx = tid; idx < 1024; idx += 256) {
            const int r = idx >> 3, ch = idx & 7;
            const size_t gsrc = (size_t)(otile * 128 + r) * KPADP + k0 + ch * 8;
            const uint32_t sdst = (uint32_t)(r * LDA + ch * 8) * 2;
            cp16(sbAh + sdst, wh + gsrc, 16);
            cp16(sbAl + sdst, wl + gsrc, 16);
        }
        for (int idx = tid; idx < 1024; idx += 256) {
            const int r = idx >> 3, ch = idx & 7;
            const size_t gsrc = ((size_t)rtile * 128 + r) * KPADP + k0 + ch * 8;
            const uint32_t sdst = (uint32_t)(r * LDA + ch * 8) * 2;
            cp16(sbBh + sdst, xh + gsrc, 16);
            cp16(sbBl + sdst, xl + gsrc, 16);
        }
        cp_commit_wait();
        __syncthreads();
#pragma unroll
        for (int ks = 0; ks < 4; ks++) {
            uint32_t ah[4][4], al[4][4], bh[8], bl[8];
#pragma unroll
            for (int mi = 0; mi < 4; mi++) {
                const uint32_t off = (uint32_t)(((aRow + mi * 16) * LDA) + aCol + ks * 16) * 2;
                ldsm_x4(ah[mi], sbAh + off);
                ldsm_x4(al[mi], sbAl + off);
            }
#pragma unroll
            for (int bi = 0; bi < 2; bi++) {
                const uint32_t off = (uint32_t)(((bRow + bi * 16) * LDA) + bCol + ks * 16) * 2;
                ldsm_x4(&bh[bi * 4], sbBh + off);
                ldsm_x4(&bl[bi * 4], sbBl + off);
            }
#pragma unroll
            for (int mi = 0; mi < 4; mi++)
#pragma unroll
                for (int ni = 0; ni < 4; ni++) {
                    mma_16816(acc[mi][ni], ah[mi], &bh[ni * 2]);
                    mma_16816(acc[mi][ni], ah[mi], &bl[ni * 2]);
                    mma_16816(acc[mi][ni], al[mi], &bh[ni * 2]);
                }
        }
    }

    // epilogue: transpose-stage, split store (no bias/gelu)
    __syncthreads();
    __nv_bfloat16* stage_hi = (__nv_bfloat16*)smem;            // [128 l][136 c]
    __nv_bfloat16* stage_lo = (__nv_bfloat16*)(smem + 36864);
    const int g = lane >> 2, tg = lane & 3;
#pragma unroll
    for (int mi = 0; mi < 4; mi++) {
        const int row0 = warp_m * 64 + mi * 16 + g;
#pragma unroll
        for (int ni = 0; ni < 4; ni++) {
            const int col = warp_n * 32 + ni * 8 + tg * 2;
#pragma unroll
            for (int e = 0; e < 4; e++) {
                const int row = row0 + ((e >> 1) << 3);        // c-local
                const int c   = col + (e & 1);                 // l-local
                __nv_bfloat16 h, l;
                split_bf16(acc[mi][ni][e], h, l);
                stage_hi[c * 136 + row] = h;
                stage_lo[c * 136 + row] = l;
            }
        }
    }
    __syncthreads();
    {
        const int row  = tid >> 1;                              // l-local
        const int half = tid & 1;
        const char* sh = (const char*)stage_hi + row * 272 + half * 128;
        const char* sl = (const char*)stage_lo + row * 272 + half * 128;
        const size_t grow = (size_t)rtile * 128 + row;          // global l row
        __nv_bfloat16* oh = out_hi + grow * HID + otile * 128 + half * 64;
        __nv_bfloat16* ol = out_lo + grow * HID + otile * 128 + half * 64;
#pragma unroll
        for (int k = 0; k < 8; k++) {
            ((uint4*)oh)[k] = ((const uint4*)sh)[k];
            ((uint4*)ol)[k] = ((const uint4*)sl)[k];
        }
    }
}

// ---------------------------------------------------------------------------
// Dilated conv layer via mma.sync bf16 split-precision (3 passes).
// 12 phases (tap outer, i-chunk inner), single-buffered 73.7KB -> 2 CTA/SM.
// ---------------------------------------------------------------------------
__global__ __launch_bounds__(256, 2) void conv_mma_kernel(
    const __nv_bfloat16* __restrict__ in_hi, const __nv_bfloat16* __restrict__ in_lo,
    const __nv_bfloat16* __restrict__ whi, const __nv_bfloat16* __restrict__ wlo,
    const float* __restrict__ bias,
    __nv_bfloat16* __restrict__ out_hi, __nv_bfloat16* __restrict__ out_lo, int d)
{
    extern __shared__ char smem[];
    const uint32_t sb = smem_u32(smem);
    const uint32_t sbAh = sb, sbAl = sb + ABUF, sbBh = sb + 2 * ABUF, sbBl = sb + 3 * ABUF;
    const int tid = threadIdx.x;
    const int wid = tid >> 5, lane = tid & 31;
    const int warp_m = wid >> 2, warp_n = wid & 3;
    const int ltile = blockIdx.x, otile = blockIdx.y, n = blockIdx.z;

    const __nv_bfloat16* Hh = in_hi + (size_t)n * HLC;
    const __nv_bfloat16* Hl = in_lo + (size_t)n * HLC;

    float acc[4][4][4];
#pragma unroll
    for (int mi = 0; mi < 4; mi++)
#pragma unroll
        for (int ni = 0; ni < 4; ni++)
#pragma unroll
            for (int e = 0; e < 4; e++) acc[mi][ni][e] = 0.f;

    const int aRow = warp_m * 64 + (lane & 15);
    const int aCol = (lane >> 4) << 3;
    const int bRow = warp_n * 32 + ((lane & 7) | ((lane >> 4) << 3));
    const int bCol = ((lane >> 3) & 1) << 3;

#pragma unroll 1
    for (int t = 0; t < 3; t++) {
        const int shift = (t - 1) * d;
#pragma unroll 1
        for (int i0 = 0; i0 < HID; i0 += 64) {
            __syncthreads();                   // prior phase's ldsm done
            // A: weight slice [128 o][64 i] hi/lo
            for (int idx = tid; idx < 1024; idx += 256) {
                const int r = idx >> 3, ch = idx & 7;
                const size_t gsrc = (size_t)t * WPLANE
                                  + (size_t)(otile * 128 + r) * HID + i0 + ch * 8;
                const uint32_t sdst = (uint32_t)(r * LDA + ch * 8) * 2;
                cp16(sbAh + sdst, whi + gsrc, 16);
                cp16(sbAl + sdst, wlo + gsrc, 16);
            }
            // B: shifted activation slice [128 l][64 i] hi/lo, zero-padded
            for (int idx = tid; idx < 1024; idx += 256) {
                const int r = idx >> 3, ch = idx & 7;
                const int lsrc = ltile * 128 + r + shift;
                const bool ok = (lsrc >= 0) && (lsrc < CHLEN);
                const size_t goff = (size_t)(ok ? lsrc : 0) * HID + i0 + ch * 8;
                const int ssz = ok ? 16 : 0;
                const uint32_t sdst = (uint32_t)(r * LDA + ch * 8) * 2;
                cp16(sbBh + sdst, Hh + goff, ssz);
                cp16(sbBl + sdst, Hl + goff, ssz);
            }
            cp_commit_wait();
            __syncthreads();
#pragma unroll
            for (int ks = 0; ks < 4; ks++) {
                uint32_t ah[4][4], al[4][4], bh[8], bl[8];
#pragma unroll
                for (int mi = 0; mi < 4; mi++) {
                    const uint32_t off = (uint32_t)(((aRow + mi * 16) * LDA) + aCol + ks * 16) * 2;
                    ldsm_x4(ah[mi], sbAh + off);
                    ldsm_x4(al[mi], sbAl + off);
                }
#pragma unroll
                for (int bi = 0; bi < 2; bi++) {
                    const uint32_t off = (uint32_t)(((bRow + bi * 16) * LDA) + bCol + ks * 16) * 2;
                    ldsm_x4(&bh[bi * 4], sbBh + off);
                    ldsm_x4(&bl[bi * 4], sbBl + off);
                }
#pragma unroll
                for (int mi = 0; mi < 4; mi++)
#pragma unroll
                    for (int ni = 0; ni < 4; ni++) {
                        mma_16816(acc[mi][ni], ah[mi], &bh[ni * 2]);  // hi*hi
                        mma_16816(acc[mi][ni], ah[mi], &bl[ni * 2]);  // hi*lo
                        mma_16816(acc[mi][ni], al[mi], &bh[ni * 2]);  // lo*hi
                    }
            }
        }
    }

    // ---- epilogue: bias + exact gelu + residual, stage [l][o], split store
    __syncthreads();
    __nv_bfloat16* stage_hi = (__nv_bfloat16*)smem;            // [128 l][136 o]
    __nv_bfloat16* stage_lo = (__nv_bfloat16*)(smem + 36864);
    const int g = lane >> 2, tg = lane & 3;
#pragma unroll
    for (int mi = 0; mi < 4; mi++) {
        const int row0 = warp_m * 64 + mi * 16 + g;
        const float b0 = bias[otile * 128 + row0];
        const float b8 = bias[otile * 128 + row0 + 8];
#pragma unroll
        for (int ni = 0; ni < 4; ni++) {
            const int col = warp_n * 32 + ni * 8 + tg * 2;
#pragma unroll
            for (int e = 0; e < 4; e++) {
                const int row = row0 + ((e >> 1) << 3);
                const int c   = col + (e & 1);
                float v = acc[mi][ni][e] + ((e < 2) ? b0 : b8);
                float r = fmaf(v, normcdff(v), v);             // gelu(v) + v
                __nv_bfloat16 h, l;
                split_bf16(r, h, l);
                stage_hi[c * 136 + row] = h;
                stage_lo[c * 136 + row] = l;
            }
        }
    }
    __syncthreads();
    {
        const int row  = tid >> 1;                              // l-local
        const int half = tid & 1;                               // o 64-half
        const char* sh = (const char*)stage_hi + row * 272 + half * 128;
        const char* sl = (const char*)stage_lo + row * 272 + half * 128;
        __nv_bfloat16* oh = out_hi + (size_t)n * HLC +
                            (size_t)(ltile * 128 + row) * HID + otile * 128 + half * 64;
        __nv_bfloat16* ol = out_lo + (size_t)n * HLC +
                            (size_t)(ltile * 128 + row) * HID + otile * 128 + half * 64;
#pragma unroll
        for (int k = 0; k < 8; k++) {
            ((uint4*)oh)[k] = ((const uint4*)sh)[k];
            ((uint4*)ol)[k] = ((const uint4*)sl)[k];
        }
    }
}

// ---------------------------------------------------------------------------
// Profile head, [l][c] layout: out[l] = b + sum_k sum_c w[c][k] h[l+k-9][c]
// ---------------------------------------------------------------------------
#define PROF_Q_ROWS 531
#define PROF_SMEM   (PROF_Q_ROWS * 20 * 4 + 16 + HID * 20 * 4)

__global__ __launch_bounds__(256) void profile_head_kernel(
    const __nv_bfloat16* __restrict__ in_hi, const __nv_bfloat16* __restrict__ in_lo,
    const float* __restrict__ wprof, const float* __restrict__ bprof,
    float* __restrict__ out)
{
    extern __shared__ char smem[];
    float* Qs  = (float*)smem;                         // [531][20]
    float* wsh = (float*)(smem + PROF_Q_ROWS * 20 * 4 + 16);
    const int n = blockIdx.x, tid = threadIdx.x;
    const int wid = tid >> 5, lane = tid & 31;

    for (int i = tid; i < HID * 20; i += 256) wsh[i] = wprof[i];
    for (int i = tid; i < PROF_Q_ROWS * 20; i += 256) Qs[i] = 0.f;
    __syncthreads();

    const __nv_bfloat16* Hh = in_hi + (size_t)n * HLC;
    const __nv_bfloat16* Hl = in_lo + (size_t)n * HLC;
    for (int row = wid; row < CHLEN; row += 8) {
        uint4 uh = *(const uint4*)(Hh + (size_t)row * HID + lane * 8);
        uint4 ul = *(const uint4*)(Hl + (size_t)row * HID + lane * 8);
        const __nv_bfloat16* ph = (const __nv_bfloat16*)&uh;
        const __nv_bfloat16* pl = (const __nv_bfloat16*)&ul;
        float acc[20];
#pragma unroll
        for (int k = 0; k < 20; k++) acc[k] = 0.f;
#pragma unroll
        for (int cc = 0; cc < 8; cc++) {
            float hv = __bfloat162float(ph[cc]) + __bfloat162float(pl[cc]);
            const float* wr = &wsh[(lane * 8 + cc) * 20];
#pragma unroll
            for (int k = 0; k < 20; k++) acc[k] = fmaf(hv, wr[k], acc[k]);
        }
#pragma unroll
        for (int off = 16; off > 0; off >>= 1)
#pragma unroll
            for (int k = 0; k < 20; k++)
                acc[k] += __shfl_xor_sync(0xFFFFFFFF, acc[k], off);
        if (lane < 20) Qs[(row + 9) * 20 + lane] = acc[lane];
    }
    __syncthreads();

    const float bz = bprof[0];
    for (int l = tid; l < CHLEN; l += 256) {
        float s = bz;
#pragma unroll
        for (int k = 0; k < 20; k++) s += Qs[(l + k) * 20 + k];
        out[NCHUNK + (size_t)n * CHLEN + l] = s;
    }
}

// ---------------------------------------------------------------------------
// atpm head, [l][c] layout; n_peaks is int32 (JAX x64-disabled)
// ---------------------------------------------------------------------------
__global__ __launch_bounds__(256) void atpm_head_kernel(
    const __nv_bfloat16* __restrict__ in_hi, const __nv_bfloat16* __restrict__ in_lo,
    const float* __restrict__ watpm, const float* __restrict__ batpm,
    const int* __restrict__ npeaks, float* __restrict__ out)
{
    __shared__ float red[256];
    const int n = blockIdx.x, tid = threadIdx.x;
    const __nv_bfloat16* Hh = in_hi + (size_t)n * HLC + tid;
    const __nv_bfloat16* Hl = in_lo + (size_t)n * HLC + tid;
    float s = 0.f;
    for (int l = 0; l < CHLEN; l++)
        s += __bfloat162float(Hh[(size_t)l * HID]) + __bfloat162float(Hl[(size_t)l * HID]);
    red[tid] = s * watpm[tid];
    __syncthreads();
    for (int off = 128; off > 0; off >>= 1) {
        if (tid < off) red[tid] += red[tid + off];
        __syncthreads();
    }
    if (tid == 0) {
        float v = red[0] * (1.f / (float)CHLEN) + batpm[0];
        int b = n >> 7, p = n & 127;
        out[n] = (p < npeaks[b]) ? v : 0.f;
    }
}

// ---------------------------------------------------------------------------
extern "C" void kernel_launch(void* const* d_in, const int* in_sizes, int n_in,
                              void* d_out, int out_size)
{
    const float* x       = (const float*)d_in[0];
    const float* w_proj  = (const float*)d_in[1];
    const float* tower_w = (const float*)d_in[2];
    const float* tower_b = (const float*)d_in[3];
    const float* w_prof  = (const float*)d_in[4];
    const float* b_prof  = (const float*)d_in[5];
    const float* w_atpm  = (const float*)d_in[6];
    const float* b_atpm  = (const float*)d_in[7];
    const int*   n_peaks = (const int*)d_in[8];
    float* out = (float*)d_out;

    __nv_bfloat16 *hiA, *loA, *hiB, *loB, *wHi, *wLo, *xHi, *xLo, *wpHi, *wpLo;
    cudaGetSymbolAddress((void**)&hiA, g_hiA);
    cudaGetSymbolAddress((void**)&loA, g_loA);
    cudaGetSymbolAddress((void**)&hiB, g_hiB);
    cudaGetSymbolAddress((void**)&loB, g_loB);
    cudaGetSymbolAddress((void**)&wHi, g_wHi);
    cudaGetSymbolAddress((void**)&wLo, g_wLo);
    cudaGetSymbolAddress((void**)&xHi, g_xHi);
    cudaGetSymbolAddress((void**)&xLo, g_xLo);
    cudaGetSymbolAddress((void**)&wpHi, g_wpHi);
    cudaGetSymbolAddress((void**)&wpLo, g_wpLo);

    cudaFuncSetAttribute(conv_mma_kernel,
                         cudaFuncAttributeMaxDynamicSharedMemorySize, SM_MMA);
    cudaFuncSetAttribute(proj_mma_kernel,
                         cudaFuncAttributeMaxDynamicSharedMemorySize, SM_MMA);
    cudaFuncSetAttribute(profile_head_kernel,
                         cudaFuncAttributeMaxDynamicSharedMemorySize, PROF_SMEM);

    wprep_kernel<<<DEPTH * 3 * WPLANE / 256, 256>>>(tower_w, wHi, wLo);
    wpsplit_kernel<<<HID, 256>>>(w_proj, wpHi, wpLo);
    xsplit_kernel<<<NROWS, 256>>>(x, xHi, xLo);
    proj_mma_kernel<<<dim3(NROWS / 128, 2), 256, SM_MMA>>>(xHi, xLo, wpHi, wpLo, hiA, loA);

    __nv_bfloat16 *ch = hiA, *cl = loA, *nh = hiB, *nl = loB;
    for (int i = 0; i < DEPTH; i++) {
        int d = 2 << i;          // 2^(i+1)
        conv_mma_kernel<<<dim3(4, 2, NCHUNK), 256, SM_MMA>>>(
            ch, cl, wHi + (size_t)i * 3 * WPLANE, wLo + (size_t)i * 3 * WPLANE,
            tower_b + i * HID, nh, nl, d);
        __nv_bfloat16* t;
        t = ch; ch = nh; nh = t;
        t = cl; cl = nl; nl = t;
    }

    profile_head_kernel<<<NCHUNK, 256, PROF_SMEM>>>(ch, cl, w_prof, b_prof, out);
    atpm_head_kernel<<<NCHUNK, 256>>>(ch, cl, w_atpm, b_atpm, n_peaks, out);
}